// round 1
// baseline (speedup 1.0000x reference)
#include <cuda_runtime.h>
#include <math.h>

#define IMG    416
#define N_ANG  320
#define N_DET  416
#define N_SAMP 416
#define PAD    244
#define PW     904                 // IMG + 2*PAD
#define NRAY   (N_ANG * N_DET)     // 133120

// Scratch (no allocation allowed in kernel_launch)
__device__ float g_pad[PW * PW];      // padded diff image (~3.27 MB)
__device__ float g_raysq[NRAY];       // per-ray squared projection value

// ---------------------------------------------------------------------------
// Kernel 1: diff + zero-pad.  g_pad[r][c] = in[r-PAD][c-PAD] - tgt[...] or 0.
// ---------------------------------------------------------------------------
__global__ void pad_kernel(const float* __restrict__ in,
                           const float* __restrict__ tgt) {
    int i = blockIdx.x * blockDim.x + threadIdx.x;
    if (i >= PW * PW) return;
    int r = i / PW;
    int c = i - r * PW;
    int rr = r - PAD;
    int cc = c - PAD;
    float v = 0.0f;
    if (rr >= 0 && rr < IMG && cc >= 0 && cc < IMG) {
        int j = rr * IMG + cc;
        v = in[j] - tgt[j];
    }
    g_pad[i] = v;
}

// ---------------------------------------------------------------------------
// Kernel 2: one thread per ray. 416-sample bilinear line integral of the
// padded diff image, then square.
// ---------------------------------------------------------------------------
__global__ void __launch_bounds__(256) ray_kernel() {
    int ray = blockIdx.x * blockDim.x + threadIdx.x;
    if (ray >= NRAY) return;

    int a = ray / N_DET;       // angle index
    int d = ray - a * N_DET;   // detector index

    // --- setup constants (double, computed once per thread; loop dominates) ---
    const double hd_d   = 208.0 * sqrt(2.0);            // half diagonal = ray_len/2
    const double gmax_d = asin(hd_d / 1075.0);
    const float  THSTEP = (float)(2.0 * M_PI / 320.0);  // matches np.float32(2pi/N_ANG)
    const float  GMAX   = (float)gmax_d;
    const float  DG     = (float)(2.0 * gmax_d / (N_DET - 1));
    const float  T0     = (float)(1075.0 - hd_d);
    const float  T1     = (float)(1075.0 + hd_d);
    const float  DTS    = (float)((2.0 * hd_d) / (N_SAMP - 1)); // linspace step == dt
    const float  CTRP   = (float)((IMG - 1) * 0.5 + PAD);       // 207.5 + PAD
    (void)T1;

    float theta = (float)a * THSTEP;
    float gamma = fmaf((float)d, DG, -GMAX);

    float sth, cth, sph, cph;
    sincosf(theta, &sth, &cth);
    sincosf(theta + gamma, &sph, &cph);

    // x_pad(t) = 1075*cos(th) + CTRP - t*cos(th+gm)
    float bx = fmaf(1075.0f, cth, CTRP);
    float by = fmaf(1075.0f, sth, CTRP);
    float ncph = -cph;
    float nsph = -sph;

    const float* __restrict__ P = g_pad;

    float acc = 0.0f;
#pragma unroll 4
    for (int s = 0; s < N_SAMP; s++) {
        float t  = fmaf((float)s, DTS, T0);
        float x  = fmaf(t, ncph, bx);
        float y  = fmaf(t, nsph, by);
        float fx = floorf(x);
        float fy = floorf(y);
        float wc = x - fx;
        float wr = y - fy;
        int   c0 = (int)fx;
        int   r0 = (int)fy;
        const float* p = P + (r0 * PW + c0);
        float v00 = __ldg(p);
        float v01 = __ldg(p + 1);
        float v10 = __ldg(p + PW);
        float v11 = __ldg(p + PW + 1);
        float top = fmaf(wc, v01 - v00, v00);
        float bot = fmaf(wc, v11 - v10, v10);
        acc = fmaf(wr, bot - top, acc + top);
    }

    float val = acc * DTS;            // * dt
    g_raysq[ray] = val * val;
}

// ---------------------------------------------------------------------------
// Kernel 3: deterministic single-block reduction -> mean * SCALE.
// ---------------------------------------------------------------------------
__global__ void reduce_kernel(float* __restrict__ out) {
    __shared__ double sm[1024];
    int tid = threadIdx.x;
    double s = 0.0;
    for (int i = tid; i < NRAY; i += 1024)
        s += (double)g_raysq[i];
    sm[tid] = s;
    __syncthreads();
    for (int stride = 512; stride > 0; stride >>= 1) {
        if (tid < stride) sm[tid] += sm[tid + stride];
        __syncthreads();
    }
    if (tid == 0) {
        const double SCALE = 512.0 / 416.0 * 0.03;
        out[0] = (float)(sm[0] / (double)NRAY * SCALE);
    }
}

// ---------------------------------------------------------------------------
extern "C" void kernel_launch(void* const* d_in, const int* in_sizes, int n_in,
                              void* d_out, int out_size) {
    const float* in  = (const float*)d_in[0];
    const float* tgt = (const float*)d_in[1];
    float* out = (float*)d_out;
    (void)in_sizes; (void)n_in; (void)out_size;

    pad_kernel<<<(PW * PW + 255) / 256, 256>>>(in, tgt);
    ray_kernel<<<(NRAY + 255) / 256, 256>>>();
    reduce_kernel<<<1, 1024>>>(out);
}

// round 3
// speedup vs baseline: 1.0306x; 1.0306x over previous
#include <cuda_runtime.h>
#include <math.h>

#define IMG    416
#define N_ANG  320
#define N_DET  416
#define N_SAMP 416
#define PAD    244
#define PW     904                  // IMG + 2*PAD
#define NRAY   (N_ANG * N_DET)      // 133120

#define TD     32                   // detectors per block
#define TS     32                   // samples per block
#define NT     13                   // 416 / 32
#define NSLOT  (NT * 2)             // 2 warp-groups per sample-chunk
#define WIN    80
#define WSTR   81                   // odd stride -> conflict-free rows

// Scratch
__device__ float g_pad[PW * PW];            // padded diff image (~3.27 MB)
__device__ float g_part[NSLOT * NRAY];      // slot-major partials (~13.8 MB)
__device__ float g_raysq[NRAY];

// ---------------------------------------------------------------------------
// Kernel 1: diff + zero-pad.
// ---------------------------------------------------------------------------
__global__ void pad_kernel(const float* __restrict__ in,
                           const float* __restrict__ tgt) {
    int i = blockIdx.x * blockDim.x + threadIdx.x;
    if (i >= PW * PW) return;
    int r = i / PW;
    int c = i - r * PW;
    int rr = r - PAD;
    int cc = c - PAD;
    float v = 0.0f;
    if (rr >= 0 && rr < IMG && cc >= 0 && cc < IMG) {
        int j = rr * IMG + cc;
        v = in[j] - tgt[j];
    }
    g_pad[i] = v;
}

// ---------------------------------------------------------------------------
// Kernel 2: SMEM-staged fan-beam projection.
// Block = (sample-chunk 32, det-group 32, angle). 256 threads, static smem.
// Stage 80x80 window, bilinear-sample 32x32 points from SMEM.
// Warp = 8 dets x 4 sample-phases; warps 0-3 -> samples 0-15, 4-7 -> 16-31.
// ---------------------------------------------------------------------------
__global__ void __launch_bounds__(256) ray_kernel() {
    __shared__ float sm[WIN * WSTR];

    const int chunk = blockIdx.x;   // 0..12
    const int dgrp  = blockIdx.y;   // 0..12
    const int a     = blockIdx.z;   // 0..319
    const int tid   = threadIdx.x;

    const double hd_d   = 208.0 * sqrt(2.0);
    const double gmax_d = asin(hd_d / 1075.0);
    const float  THSTEP = (float)(2.0 * M_PI / 320.0);
    const float  GMAX   = (float)gmax_d;
    const float  DG     = (float)(2.0 * gmax_d / (N_DET - 1));
    const float  T0     = (float)(1075.0 - hd_d);
    const float  DTS    = (float)((2.0 * hd_d) / (N_SAMP - 1));
    const float  CTRP   = (float)((IMG - 1) * 0.5 + PAD);   // 451.5

    const float theta = (float)a * THSTEP;
    float sth, cth;
    sincosf(theta, &sth, &cth);
    const float bx = fmaf(1075.0f, cth, CTRP);
    const float by = fmaf(1075.0f, sth, CTRP);

    // bbox from the 4 corner rays
    const float g_lo = fmaf((float)(dgrp * TD), DG, -GMAX);
    const float g_hi = g_lo + (float)(TD - 1) * DG;
    const float t_lo = fmaf((float)(chunk * TS), DTS, T0);
    const float t_hi = t_lo + (float)(TS - 1) * DTS;

    float s1, c1, s2, c2;
    sincosf(theta + g_lo, &s1, &c1);
    sincosf(theta + g_hi, &s2, &c2);

    float x11 = fmaf(-t_lo, c1, bx), y11 = fmaf(-t_lo, s1, by);
    float x12 = fmaf(-t_hi, c1, bx), y12 = fmaf(-t_hi, s1, by);
    float x21 = fmaf(-t_lo, c2, bx), y21 = fmaf(-t_lo, s2, by);
    float x22 = fmaf(-t_hi, c2, bx), y22 = fmaf(-t_hi, s2, by);

    float xmin = fminf(fminf(x11, x12), fminf(x21, x22));
    float ymin = fminf(fminf(y11, y12), fminf(y21, y22));

    int cmin = (int)floorf(xmin) - 2;
    int rmin = (int)floorf(ymin) - 2;
    cmin = max(0, min(cmin, PW - WIN));
    rmin = max(0, min(rmin, PW - WIN));

    // stage 80x80 window (coalesced; rows contiguous in g_pad)
    const float* __restrict__ src = g_pad + rmin * PW + cmin;
    #pragma unroll 5
    for (int idx = tid; idx < WIN * WIN; idx += 256) {
        int rr = idx / WIN;
        int cc = idx - rr * WIN;
        sm[rr * WSTR + cc] = __ldg(src + rr * PW + cc);
    }
    __syncthreads();

    // compute
    const int warp   = tid >> 5;
    const int lane   = tid & 31;
    const int sgroup = warp >> 2;                    // 0 or 1
    const int det    = dgrp * TD + (warp & 3) * 8 + (lane >> 2);
    const int sphase = lane & 3;

    const float gamma = fmaf((float)det, DG, -GMAX);
    float sph, cph;
    sincosf(theta + gamma, &sph, &cph);
    const float bxl  = bx - (float)cmin;
    const float byl  = by - (float)rmin;
    const float ncph = -cph;
    const float nsph = -sph;

    const int s_base = chunk * TS + sgroup * 16 + sphase;

    float acc = 0.0f;
    #pragma unroll
    for (int i = 0; i < 4; i++) {
        float t  = fmaf((float)(s_base + 4 * i), DTS, T0);
        float x  = fmaf(t, ncph, bxl);
        float y  = fmaf(t, nsph, byl);
        float fx = floorf(x);
        float fy = floorf(y);
        float wc = x - fx;
        float wr = y - fy;
        int addr = (int)fy * WSTR + (int)fx;
        float v00 = sm[addr];
        float v01 = sm[addr + 1];
        float v10 = sm[addr + WSTR];
        float v11 = sm[addr + WSTR + 1];
        float top = fmaf(wc, v01 - v00, v00);
        float bot = fmaf(wc, v11 - v10, v10);
        acc = fmaf(wr, bot - top, acc + top);
    }

    // reduce 4 phases per detector
    acc += __shfl_xor_sync(0xFFFFFFFFu, acc, 1);
    acc += __shfl_xor_sync(0xFFFFFFFFu, acc, 2);

    if (sphase == 0) {
        int slot = chunk * 2 + sgroup;
        g_part[slot * NRAY + a * N_DET + det] = acc;
    }
}

// ---------------------------------------------------------------------------
// Kernel 3a: per-ray sum of 26 slots (coalesced), square, * dt^2.
// ---------------------------------------------------------------------------
__global__ void raysum_kernel() {
    int ray = blockIdx.x * blockDim.x + threadIdx.x;
    if (ray >= NRAY) return;
    const double hd_d = 208.0 * sqrt(2.0);
    const float  DTS  = (float)((2.0 * hd_d) / (N_SAMP - 1));
    float v = 0.0f;
    #pragma unroll
    for (int s = 0; s < NSLOT; s++)
        v += g_part[s * NRAY + ray];
    float val = v * DTS;
    g_raysq[ray] = val * val;
}

// ---------------------------------------------------------------------------
// Kernel 3b: deterministic tree reduction -> mean * SCALE.
// ---------------------------------------------------------------------------
__global__ void reduce_kernel(float* __restrict__ out) {
    __shared__ double smr[1024];
    int tid = threadIdx.x;
    double s = 0.0;
    for (int i = tid; i < NRAY; i += 1024)
        s += (double)g_raysq[i];
    smr[tid] = s;
    __syncthreads();
    for (int stride = 512; stride > 0; stride >>= 1) {
        if (tid < stride) smr[tid] += smr[tid + stride];
        __syncthreads();
    }
    if (tid == 0) {
        const double SCALE = 512.0 / 416.0 * 0.03;
        out[0] = (float)(smr[0] / (double)NRAY * SCALE);
    }
}

// ---------------------------------------------------------------------------
extern "C" void kernel_launch(void* const* d_in, const int* in_sizes, int n_in,
                              void* d_out, int out_size) {
    const float* in  = (const float*)d_in[0];
    const float* tgt = (const float*)d_in[1];
    float* out = (float*)d_out;
    (void)in_sizes; (void)n_in; (void)out_size;

    pad_kernel<<<(PW * PW + 255) / 256, 256>>>(in, tgt);
    ray_kernel<<<dim3(NT, NT, N_ANG), 256>>>();
    raysum_kernel<<<(NRAY + 255) / 256, 256>>>();
    reduce_kernel<<<1, 1024>>>(out);
}

// round 4
// speedup vs baseline: 1.6695x; 1.6198x over previous
#include <cuda_runtime.h>
#include <math.h>

#define IMG    416
#define N_ANG  320
#define N_DET  416
#define N_SAMP 416
#define PAD    244
#define PW     904                  // IMG + 2*PAD
#define NRAY   (N_ANG * N_DET)      // 133120

#define TD     64                   // detectors per block
#define TS     64                   // samples per block
#define NDG    7                    // ceil(416/64)
#define NSC    7                    // ceil(416/64)
#define WIN    160                  // staged window (needs >= ~152 incl. margins)
#define WSTR   164                  // mult-of-4 stride, 4-bank shift per row
#define SMEM_BYTES (WIN * WSTR * 4) // 104,960 B
#define NBLK_R 520                  // NRAY / 256

// Scratch
__device__ float  g_pad[PW * PW];           // padded diff image (~3.27 MB)
__device__ float  g_part[NSC * NRAY];       // slot-major per-(chunk, ray) partials
__device__ double g_blk[NBLK_R];            // per-block reduction partials

// ---------------------------------------------------------------------------
// Kernel 1: diff + zero-pad.
// ---------------------------------------------------------------------------
__global__ void pad_kernel(const float* __restrict__ in,
                           const float* __restrict__ tgt) {
    int i = blockIdx.x * blockDim.x + threadIdx.x;
    if (i >= PW * PW) return;
    int r = i / PW;
    int c = i - r * PW;
    int rr = r - PAD;
    int cc = c - PAD;
    float v = 0.0f;
    if (rr >= 0 && rr < IMG && cc >= 0 && cc < IMG) {
        int j = rr * IMG + cc;
        v = in[j] - tgt[j];
    }
    g_pad[i] = v;
}

// ---------------------------------------------------------------------------
// Kernel 2: SMEM-staged fan-beam projection.
// Block = (sample-chunk 64, det-group 64, angle), 256 threads, 104 KB dyn smem.
// Thread 0 computes the clamped window origin; all threads stage via float4;
// warp = 8 dets x 4 sample-phases, 16 samples per thread.
// ---------------------------------------------------------------------------
__global__ void __launch_bounds__(256, 2) ray_kernel() {
    extern __shared__ float sm[];
    __shared__ int   sh_cmin, sh_rmin;
    __shared__ float sh_bx, sh_by;

    const int chunk = blockIdx.x;   // 0..6
    const int dgrp  = blockIdx.y;   // 0..6
    const int a     = blockIdx.z;   // 0..319
    const int tid   = threadIdx.x;

    const double hd_d   = 208.0 * sqrt(2.0);
    const double gmax_d = asin(hd_d / 1075.0);
    const float  THSTEP = (float)(2.0 * M_PI / 320.0);
    const float  GMAX   = (float)gmax_d;
    const float  DG     = (float)(2.0 * gmax_d / (N_DET - 1));
    const float  T0     = (float)(1075.0 - hd_d);
    const float  DTS    = (float)((2.0 * hd_d) / (N_SAMP - 1));
    const float  CTRP   = (float)((IMG - 1) * 0.5 + PAD);   // 451.5

    const float theta = (float)a * THSTEP;

    if (tid == 0) {
        float sth, cth;
        sincosf(theta, &sth, &cth);
        float bx = fmaf(1075.0f, cth, CTRP);
        float by = fmaf(1075.0f, sth, CTRP);

        // bbox corners from VALID index extremes only (clamp edge tiles)
        int d_lo = dgrp * TD;
        int d_hi = min(d_lo + TD - 1, N_DET - 1);
        int s_lo = chunk * TS;
        int s_hi = min(s_lo + TS - 1, N_SAMP - 1);
        float g_lo = fmaf((float)d_lo, DG, -GMAX);
        float g_hi = fmaf((float)d_hi, DG, -GMAX);
        float t_lo = fmaf((float)s_lo, DTS, T0);
        float t_hi = fmaf((float)s_hi, DTS, T0);

        float s1, c1, s2, c2;
        sincosf(theta + g_lo, &s1, &c1);
        sincosf(theta + g_hi, &s2, &c2);

        float x11 = fmaf(-t_lo, c1, bx), y11 = fmaf(-t_lo, s1, by);
        float x12 = fmaf(-t_hi, c1, bx), y12 = fmaf(-t_hi, s1, by);
        float x21 = fmaf(-t_lo, c2, bx), y21 = fmaf(-t_lo, s2, by);
        float x22 = fmaf(-t_hi, c2, bx), y22 = fmaf(-t_hi, s2, by);

        float xmin = fminf(fminf(x11, x12), fminf(x21, x22));
        float ymin = fminf(fminf(y11, y12), fminf(y21, y22));

        int cmin = ((int)floorf(xmin) - 2);
        int rmin = ((int)floorf(ymin) - 2);
        cmin = max(0, min(cmin, PW - WIN)) & ~3;   // 4-aligned for float4
        rmin = max(0, min(rmin, PW - WIN));
        sh_cmin = cmin;
        sh_rmin = rmin;
        sh_bx = bx;
        sh_by = by;
    }
    __syncthreads();

    const int cmin = sh_cmin;
    const int rmin = sh_rmin;

    // stage 160x160 window via float4 (rows 16B-aligned in src and smem)
    {
        const float4* __restrict__ src =
            (const float4*)(g_pad + rmin * PW + cmin);
        float4* dst = (float4*)sm;
        #pragma unroll 5
        for (int idx = tid; idx < WIN * (WIN / 4); idx += 256) {
            int rr = idx / (WIN / 4);
            int cc = idx - rr * (WIN / 4);
            dst[rr * (WSTR / 4) + cc] = src[rr * (PW / 4) + cc];
        }
    }
    __syncthreads();

    // compute: warp w handles dets [dgrp*64 + w*8, +8), lane phases 0..3
    const int warp   = tid >> 5;
    const int lane   = tid & 31;
    const int det    = dgrp * TD + warp * 8 + (lane >> 2);
    const int sphase = lane & 3;

    float acc = 0.0f;
    if (det < N_DET) {
        const float gamma = fmaf((float)det, DG, -GMAX);
        float sph, cph;
        sincosf(theta + gamma, &sph, &cph);
        const float bxl  = sh_bx - (float)cmin;
        const float byl  = sh_by - (float)rmin;
        const float ncph = -cph;
        const float nsph = -sph;

        const int s_base = chunk * TS + sphase;
        const int niter  = (chunk == NSC - 1) ? 8 : 16;  // last chunk: 32 samples

        #pragma unroll 8
        for (int i = 0; i < niter; i++) {
            float t  = fmaf((float)(s_base + 4 * i), DTS, T0);
            float x  = fmaf(t, ncph, bxl);
            float y  = fmaf(t, nsph, byl);
            float fx = floorf(x);
            float fy = floorf(y);
            float wc = x - fx;
            float wr = y - fy;
            int addr = (int)fy * WSTR + (int)fx;
            float v00 = sm[addr];
            float v01 = sm[addr + 1];
            float v10 = sm[addr + WSTR];
            float v11 = sm[addr + WSTR + 1];
            float top = fmaf(wc, v01 - v00, v00);
            float bot = fmaf(wc, v11 - v10, v10);
            acc = fmaf(wr, bot - top, acc + top);
        }
    }

    // reduce 4 phases per detector
    acc += __shfl_xor_sync(0xFFFFFFFFu, acc, 1);
    acc += __shfl_xor_sync(0xFFFFFFFFu, acc, 2);

    if (sphase == 0 && det < N_DET) {
        g_part[chunk * NRAY + a * N_DET + det] = acc;
    }
}

// ---------------------------------------------------------------------------
// Kernel 3a: per-ray chunk sum + square, then per-block tree reduce (double).
// ---------------------------------------------------------------------------
__global__ void raysum_kernel() {
    __shared__ double smr[256];
    const double hd_d = 208.0 * sqrt(2.0);
    const float  DTS  = (float)((2.0 * hd_d) / (N_SAMP - 1));
    int tid = threadIdx.x;
    int ray = blockIdx.x * 256 + tid;

    float v = 0.0f;
    #pragma unroll
    for (int s = 0; s < NSC; s++)
        v += g_part[s * NRAY + ray];
    float val = v * DTS;
    smr[tid] = (double)val * (double)val;
    __syncthreads();
    for (int stride = 128; stride > 0; stride >>= 1) {
        if (tid < stride) smr[tid] += smr[tid + stride];
        __syncthreads();
    }
    if (tid == 0) g_blk[blockIdx.x] = smr[0];
}

// ---------------------------------------------------------------------------
// Kernel 3b: final deterministic reduction -> mean * SCALE.
// ---------------------------------------------------------------------------
__global__ void reduce_kernel(float* __restrict__ out) {
    __shared__ double smr[1024];
    int tid = threadIdx.x;
    smr[tid] = (tid < NBLK_R) ? g_blk[tid] : 0.0;
    __syncthreads();
    for (int stride = 512; stride > 0; stride >>= 1) {
        if (tid < stride) smr[tid] += smr[tid + stride];
        __syncthreads();
    }
    if (tid == 0) {
        const double SCALE = 512.0 / 416.0 * 0.03;
        out[0] = (float)(smr[0] / (double)NRAY * SCALE);
    }
}

// ---------------------------------------------------------------------------
extern "C" void kernel_launch(void* const* d_in, const int* in_sizes, int n_in,
                              void* d_out, int out_size) {
    const float* in  = (const float*)d_in[0];
    const float* tgt = (const float*)d_in[1];
    float* out = (float*)d_out;
    (void)in_sizes; (void)n_in; (void)out_size;

    static int configured = 0;
    if (!configured) {
        cudaFuncSetAttribute(ray_kernel,
                             cudaFuncAttributeMaxDynamicSharedMemorySize,
                             SMEM_BYTES);
        configured = 1;
    }

    pad_kernel<<<(PW * PW + 255) / 256, 256>>>(in, tgt);
    ray_kernel<<<dim3(NSC, NDG, N_ANG), 256, SMEM_BYTES>>>();
    raysum_kernel<<<NBLK_R, 256>>>();
    reduce_kernel<<<1, 1024>>>(out);
}

// round 7
// speedup vs baseline: 1.8261x; 1.0938x over previous
#include <cuda_runtime.h>
#include <math.h>

#define IMG    416
#define N_ANG  320
#define N_DET  416
#define N_SAMP 416
#define PAD    244
#define PW     904                  // IMG + 2*PAD
#define NRAY   (N_ANG * N_DET)      // 133120

#define AGRP   4                    // angles per block
#define NAG    (N_ANG / AGRP)       // 80
#define TD     64                   // detectors per block
#define TS     64                   // samples per block
#define NDG    7                    // ceil(416/64)
#define NSC    7                    // ceil(416/64)
#define WIN    188                  // staged window (needs ~180 incl. margins)
#define WSTR   196                  // mult-of-4 stride; 196 mod 32 = 4 -> row bank shift
#define SMEM_BYTES (WIN * WSTR * 4) // 147,392 B
#define NBLK_R 520                  // NRAY / 256

// Scratch
__device__ float  g_pad[PW * PW];           // padded diff image (~3.27 MB)
__device__ float  g_part[NSC * NRAY];       // slot-major per-(chunk, ray) partials
__device__ double g_blk[NBLK_R];            // per-block reduction partials

// ---------------------------------------------------------------------------
// Kernel 1: diff + zero-pad.
// ---------------------------------------------------------------------------
__global__ void pad_kernel(const float* __restrict__ in,
                           const float* __restrict__ tgt) {
    int i = blockIdx.x * blockDim.x + threadIdx.x;
    if (i >= PW * PW) return;
    int r = i / PW;
    int c = i - r * PW;
    int rr = r - PAD;
    int cc = c - PAD;
    float v = 0.0f;
    if (rr >= 0 && rr < IMG && cc >= 0 && cc < IMG) {
        int j = rr * IMG + cc;
        v = in[j] - tgt[j];
    }
    g_pad[i] = v;
}

// ---------------------------------------------------------------------------
// Kernel 2: SMEM-staged fan-beam projection, 4 angles per staged window.
// Block = (sample-chunk 64, det-group 64, angle-group of 4). 1024 threads.
// Warp w (0..31): angle = ag*4 + (w & 3), det octet = (w >> 2) in [0,7];
// lane = 8 dets x 4 sample-phases. 16 samples per thread.
// Out-of-range detectors (dgrp=6, det>=416) are masked: warp-uniform branch.
// ---------------------------------------------------------------------------
__global__ void __launch_bounds__(1024, 1) ray_kernel() {
    extern __shared__ float sm[];
    __shared__ int sh_cmin, sh_rmin;

    const int chunk = blockIdx.x;   // 0..6
    const int dgrp  = blockIdx.y;   // 0..6
    const int ag    = blockIdx.z;   // 0..79
    const int tid   = threadIdx.x;

    const double hd_d   = 208.0 * sqrt(2.0);
    const double gmax_d = asin(hd_d / 1075.0);
    const float  THSTEP = (float)(2.0 * M_PI / 320.0);
    const float  GMAX   = (float)gmax_d;
    const float  DG     = (float)(2.0 * gmax_d / (N_DET - 1));
    const float  T0     = (float)(1075.0 - hd_d);
    const float  DTS    = (float)((2.0 * hd_d) / (N_SAMP - 1));
    const float  CTRP   = (float)((IMG - 1) * 0.5 + PAD);   // 451.5

    if (tid == 0) {
        // bbox over the 8 corner rays of the two extreme angles of this group
        // (intermediate angles covered by sagitta < 0.2 px, inside margin).
        int d_lo = dgrp * TD;
        int d_hi = min(d_lo + TD - 1, N_DET - 1);
        int s_lo = chunk * TS;
        int s_hi = min(s_lo + TS - 1, N_SAMP - 1);
        float g_lo = fmaf((float)d_lo, DG, -GMAX);
        float g_hi = fmaf((float)d_hi, DG, -GMAX);
        float t_lo = fmaf((float)s_lo, DTS, T0);
        float t_hi = fmaf((float)s_hi, DTS, T0);

        float xmin = 1e30f, ymin = 1e30f;
        #pragma unroll
        for (int k = 0; k < 2; k++) {
            float th = (float)(ag * AGRP + k * (AGRP - 1)) * THSTEP;
            float sth, cth;
            sincosf(th, &sth, &cth);
            float bx = fmaf(1075.0f, cth, CTRP);
            float by = fmaf(1075.0f, sth, CTRP);
            float s1, c1, s2, c2;
            sincosf(th + g_lo, &s1, &c1);
            sincosf(th + g_hi, &s2, &c2);
            xmin = fminf(xmin, fminf(fminf(fmaf(-t_lo, c1, bx), fmaf(-t_hi, c1, bx)),
                                     fminf(fmaf(-t_lo, c2, bx), fmaf(-t_hi, c2, bx))));
            ymin = fminf(ymin, fminf(fminf(fmaf(-t_lo, s1, by), fmaf(-t_hi, s1, by)),
                                     fminf(fmaf(-t_lo, s2, by), fmaf(-t_hi, s2, by))));
        }

        int cmin = (int)floorf(xmin) - 2;
        int rmin = (int)floorf(ymin) - 2;
        sh_cmin = max(0, min(cmin, PW - WIN)) & ~3;   // 4-aligned for float4
        sh_rmin = max(0, min(rmin, PW - WIN));
    }
    __syncthreads();

    const int cmin = sh_cmin;
    const int rmin = sh_rmin;

    // stage WIN x WIN window via float4 (WIN/4 = 47)
    {
        const float4* __restrict__ src =
            (const float4*)(g_pad + rmin * PW + cmin);
        float4* dst = (float4*)sm;
        #pragma unroll 4
        for (int idx = tid; idx < WIN * (WIN / 4); idx += 1024) {
            int rr = idx / (WIN / 4);
            int cc = idx - rr * (WIN / 4);
            dst[rr * (WSTR / 4) + cc] = src[rr * (PW / 4) + cc];
        }
    }
    __syncthreads();

    // compute
    const int warp   = tid >> 5;
    const int lane   = tid & 31;
    const int a      = ag * AGRP + (warp & 3);
    const int det    = dgrp * TD + (warp >> 2) * 8 + (lane >> 2);
    const int sphase = lane & 3;

    float acc = 0.0f;
    if (det < N_DET) {
        const float theta = (float)a * THSTEP;
        float sth, cth;
        sincosf(theta, &sth, &cth);
        const float gamma = fmaf((float)det, DG, -GMAX);
        float sph, cph;
        sincosf(theta + gamma, &sph, &cph);

        const float bxl  = fmaf(1075.0f, cth, CTRP) - (float)cmin;
        const float byl  = fmaf(1075.0f, sth, CTRP) - (float)rmin;
        const float ncph = -cph;
        const float nsph = -sph;

        const int s_base = chunk * TS + sphase;
        const int niter  = (chunk == NSC - 1) ? 8 : 16;  // last chunk: 32 samples

        #pragma unroll 8
        for (int i = 0; i < niter; i++) {
            float t  = fmaf((float)(s_base + 4 * i), DTS, T0);
            float x  = fmaf(t, ncph, bxl);
            float y  = fmaf(t, nsph, byl);
            float fx = floorf(x);
            float fy = floorf(y);
            float wc = x - fx;
            float wr = y - fy;
            int addr = (int)fy * WSTR + (int)fx;
            float v00 = sm[addr];
            float v01 = sm[addr + 1];
            float v10 = sm[addr + WSTR];
            float v11 = sm[addr + WSTR + 1];
            float top = fmaf(wc, v01 - v00, v00);
            float bot = fmaf(wc, v11 - v10, v10);
            acc = fmaf(wr, bot - top, acc + top);
        }
    }

    // reduce 4 phases per detector
    acc += __shfl_xor_sync(0xFFFFFFFFu, acc, 1);
    acc += __shfl_xor_sync(0xFFFFFFFFu, acc, 2);

    if (sphase == 0 && det < N_DET) {
        g_part[chunk * NRAY + a * N_DET + det] = acc;
    }
}

// ---------------------------------------------------------------------------
// Kernel 3a: per-ray chunk sum + square, per-block tree reduce (double).
// ---------------------------------------------------------------------------
__global__ void raysum_kernel() {
    __shared__ double smr[256];
    const double hd_d = 208.0 * sqrt(2.0);
    const float  DTS  = (float)((2.0 * hd_d) / (N_SAMP - 1));
    int tid = threadIdx.x;
    int ray = blockIdx.x * 256 + tid;

    float v = 0.0f;
    #pragma unroll
    for (int s = 0; s < NSC; s++)
        v += g_part[s * NRAY + ray];
    float val = v * DTS;
    smr[tid] = (double)val * (double)val;
    __syncthreads();
    for (int stride = 128; stride > 0; stride >>= 1) {
        if (tid < stride) smr[tid] += smr[tid + stride];
        __syncthreads();
    }
    if (tid == 0) g_blk[blockIdx.x] = smr[0];
}

// ---------------------------------------------------------------------------
// Kernel 3b: final deterministic reduction -> mean * SCALE.
// ---------------------------------------------------------------------------
__global__ void reduce_kernel(float* __restrict__ out) {
    __shared__ double smr[1024];
    int tid = threadIdx.x;
    smr[tid] = (tid < NBLK_R) ? g_blk[tid] : 0.0;
    __syncthreads();
    for (int stride = 512; stride > 0; stride >>= 1) {
        if (tid < stride) smr[tid] += smr[tid + stride];
        __syncthreads();
    }
    if (tid == 0) {
        const double SCALE = 512.0 / 416.0 * 0.03;
        out[0] = (float)(smr[0] / (double)NRAY * SCALE);
    }
}

// ---------------------------------------------------------------------------
extern "C" void kernel_launch(void* const* d_in, const int* in_sizes, int n_in,
                              void* d_out, int out_size) {
    const float* in  = (const float*)d_in[0];
    const float* tgt = (const float*)d_in[1];
    float* out = (float*)d_out;
    (void)in_sizes; (void)n_in; (void)out_size;

    static int configured = 0;
    if (!configured) {
        cudaFuncSetAttribute(ray_kernel,
                             cudaFuncAttributeMaxDynamicSharedMemorySize,
                             SMEM_BYTES);
        configured = 1;
    }

    pad_kernel<<<(PW * PW + 255) / 256, 256>>>(in, tgt);
    ray_kernel<<<dim3(NSC, NDG, NAG), 1024, SMEM_BYTES>>>();
    raysum_kernel<<<NBLK_R, 256>>>();
    reduce_kernel<<<1, 1024>>>(out);
}

// round 8
// speedup vs baseline: 1.8963x; 1.0384x over previous
#include <cuda_runtime.h>
#include <cuda_fp16.h>
#include <math.h>

#define IMG    416
#define N_ANG  320
#define N_DET  416
#define N_SAMP 416
#define PAD    244
#define PW     904                  // IMG + 2*PAD
#define NRAY   (N_ANG * N_DET)      // 133120

#define AGRP   4                    // angles per block
#define NAG    (N_ANG / AGRP)       // 80
#define TD     64                   // detectors per block
#define TS     64                   // samples per block
#define NDG    7                    // ceil(416/64)
#define NSC    7                    // ceil(416/64)
#define WIN    188                  // staged window (needs ~180 incl. margins)
#define WSTR   196                  // stride in half2 words; 196 mod 32 = 4 bank shift
#define SMEM_BYTES (WIN * WSTR * 4) // 147,392 B (half2 = 4 B/word)
#define NBLK_R 520                  // NRAY / 256

// Scratch: packed image, g_padh[i] = half2( v[i], v[i+1 within row] )
__device__ __align__(16) __half2 g_padh[PW * PW];   // ~3.27 MB
__device__ float  g_part[NSC * NRAY];               // per-(chunk, ray) partials
__device__ double g_blk[NBLK_R];

// ---------------------------------------------------------------------------
// Kernel 1: diff + zero-pad + pack into half2 pixel pairs.
// ---------------------------------------------------------------------------
__device__ __forceinline__ float diffv(const float* in, const float* tgt,
                                       int r, int c) {
    int rr = r - PAD;
    int cc = c - PAD;
    if (rr >= 0 && rr < IMG && cc >= 0 && cc < IMG) {
        int j = rr * IMG + cc;
        return in[j] - tgt[j];
    }
    return 0.0f;
}

__global__ void pad_kernel(const float* __restrict__ in,
                           const float* __restrict__ tgt) {
    int i = blockIdx.x * blockDim.x + threadIdx.x;
    if (i >= PW * PW) return;
    int r = i / PW;
    int c = i - r * PW;
    float v0 = diffv(in, tgt, r, c);
    float v1 = diffv(in, tgt, r, c + 1);   // c+1==PW -> out of image -> 0 (unused anyway)
    g_padh[i] = __floats2half2_rn(v0, v1);
}

// ---------------------------------------------------------------------------
// Kernel 2: SMEM-staged fan-beam projection, 4 angles per staged window.
// Identical geometry/mapping to the passing R7 kernel; storage is half2
// pixel-pairs so each bilinear sample needs only 2 LDS.32.
// ---------------------------------------------------------------------------
__global__ void __launch_bounds__(1024, 1) ray_kernel() {
    extern __shared__ __half2 smh[];
    __shared__ int sh_cmin, sh_rmin;

    const int chunk = blockIdx.x;   // 0..6
    const int dgrp  = blockIdx.y;   // 0..6
    const int ag    = blockIdx.z;   // 0..79
    const int tid   = threadIdx.x;

    const double hd_d   = 208.0 * sqrt(2.0);
    const double gmax_d = asin(hd_d / 1075.0);
    const float  THSTEP = (float)(2.0 * M_PI / 320.0);
    const float  GMAX   = (float)gmax_d;
    const float  DG     = (float)(2.0 * gmax_d / (N_DET - 1));
    const float  T0     = (float)(1075.0 - hd_d);
    const float  DTS    = (float)((2.0 * hd_d) / (N_SAMP - 1));
    const float  CTRP   = (float)((IMG - 1) * 0.5 + PAD);   // 451.5

    if (tid == 0) {
        int d_lo = dgrp * TD;
        int d_hi = min(d_lo + TD - 1, N_DET - 1);
        int s_lo = chunk * TS;
        int s_hi = min(s_lo + TS - 1, N_SAMP - 1);
        float g_lo = fmaf((float)d_lo, DG, -GMAX);
        float g_hi = fmaf((float)d_hi, DG, -GMAX);
        float t_lo = fmaf((float)s_lo, DTS, T0);
        float t_hi = fmaf((float)s_hi, DTS, T0);

        float xmin = 1e30f, ymin = 1e30f;
        #pragma unroll
        for (int k = 0; k < 2; k++) {
            float th = (float)(ag * AGRP + k * (AGRP - 1)) * THSTEP;
            float sth, cth;
            sincosf(th, &sth, &cth);
            float bx = fmaf(1075.0f, cth, CTRP);
            float by = fmaf(1075.0f, sth, CTRP);
            float s1, c1, s2, c2;
            sincosf(th + g_lo, &s1, &c1);
            sincosf(th + g_hi, &s2, &c2);
            xmin = fminf(xmin, fminf(fminf(fmaf(-t_lo, c1, bx), fmaf(-t_hi, c1, bx)),
                                     fminf(fmaf(-t_lo, c2, bx), fmaf(-t_hi, c2, bx))));
            ymin = fminf(ymin, fminf(fminf(fmaf(-t_lo, s1, by), fmaf(-t_hi, s1, by)),
                                     fminf(fmaf(-t_lo, s2, by), fmaf(-t_hi, s2, by))));
        }

        int cmin = (int)floorf(xmin) - 2;
        int rmin = (int)floorf(ymin) - 2;
        sh_cmin = max(0, min(cmin, PW - WIN)) & ~3;   // 16B-aligned for uint4
        sh_rmin = max(0, min(rmin, PW - WIN));
    }
    __syncthreads();

    const int cmin = sh_cmin;
    const int rmin = sh_rmin;

    // stage WIN x WIN half2 words via uint4 (4 words = 16 B; WIN/4 = 47)
    {
        const uint4* __restrict__ src =
            (const uint4*)(g_padh + rmin * PW + cmin);
        uint4* dst = (uint4*)smh;
        #pragma unroll 4
        for (int idx = tid; idx < WIN * (WIN / 4); idx += 1024) {
            int rr = idx / (WIN / 4);
            int cc = idx - rr * (WIN / 4);
            dst[rr * (WSTR / 4) + cc] = src[rr * (PW / 4) + cc];
        }
    }
    __syncthreads();

    // compute: warp w: angle = ag*4 + (w&3), det octet = w>>3.. (w>>2) in [0,7]
    const int warp   = tid >> 5;
    const int lane   = tid & 31;
    const int a      = ag * AGRP + (warp & 3);
    const int det    = dgrp * TD + (warp >> 2) * 8 + (lane >> 2);
    const int sphase = lane & 3;

    float acc = 0.0f;
    if (det < N_DET) {
        const float theta = (float)a * THSTEP;
        float sth, cth;
        sincosf(theta, &sth, &cth);
        const float gamma = fmaf((float)det, DG, -GMAX);
        float sph, cph;
        sincosf(theta + gamma, &sph, &cph);

        const float bxl  = fmaf(1075.0f, cth, CTRP) - (float)cmin;
        const float byl  = fmaf(1075.0f, sth, CTRP) - (float)rmin;
        const float ncph = -cph;
        const float nsph = -sph;

        const int s_base = chunk * TS + sphase;
        const int niter  = (chunk == NSC - 1) ? 8 : 16;  // last chunk: 32 samples

        #pragma unroll 8
        for (int i = 0; i < niter; i++) {
            float t  = fmaf((float)(s_base + 4 * i), DTS, T0);
            float x  = fmaf(t, ncph, bxl);
            float y  = fmaf(t, nsph, byl);
            float fx = floorf(x);
            float fy = floorf(y);
            float wc = x - fx;
            float wr = y - fy;
            int addr = (int)fy * WSTR + (int)fx;
            float2 tp = __half22float2(smh[addr]);          // (v00, v01)
            float2 bt = __half22float2(smh[addr + WSTR]);   // (v10, v11)
            float top = fmaf(wc, tp.y - tp.x, tp.x);
            float bot = fmaf(wc, bt.y - bt.x, bt.x);
            acc = fmaf(wr, bot - top, acc + top);
        }
    }

    // reduce 4 phases per detector
    acc += __shfl_xor_sync(0xFFFFFFFFu, acc, 1);
    acc += __shfl_xor_sync(0xFFFFFFFFu, acc, 2);

    if (sphase == 0 && det < N_DET) {
        g_part[chunk * NRAY + a * N_DET + det] = acc;
    }
}

// ---------------------------------------------------------------------------
// Kernel 3a: per-ray chunk sum + square, per-block tree reduce (double).
// ---------------------------------------------------------------------------
__global__ void raysum_kernel() {
    __shared__ double smr[256];
    const double hd_d = 208.0 * sqrt(2.0);
    const float  DTS  = (float)((2.0 * hd_d) / (N_SAMP - 1));
    int tid = threadIdx.x;
    int ray = blockIdx.x * 256 + tid;

    float v = 0.0f;
    #pragma unroll
    for (int s = 0; s < NSC; s++)
        v += g_part[s * NRAY + ray];
    float val = v * DTS;
    smr[tid] = (double)val * (double)val;
    __syncthreads();
    for (int stride = 128; stride > 0; stride >>= 1) {
        if (tid < stride) smr[tid] += smr[tid + stride];
        __syncthreads();
    }
    if (tid == 0) g_blk[blockIdx.x] = smr[0];
}

// ---------------------------------------------------------------------------
// Kernel 3b: final deterministic reduction -> mean * SCALE.
// ---------------------------------------------------------------------------
__global__ void reduce_kernel(float* __restrict__ out) {
    __shared__ double smr[1024];
    int tid = threadIdx.x;
    smr[tid] = (tid < NBLK_R) ? g_blk[tid] : 0.0;
    __syncthreads();
    for (int stride = 512; stride > 0; stride >>= 1) {
        if (tid < stride) smr[tid] += smr[tid + stride];
        __syncthreads();
    }
    if (tid == 0) {
        const double SCALE = 512.0 / 416.0 * 0.03;
        out[0] = (float)(smr[0] / (double)NRAY * SCALE);
    }
}

// ---------------------------------------------------------------------------
extern "C" void kernel_launch(void* const* d_in, const int* in_sizes, int n_in,
                              void* d_out, int out_size) {
    const float* in  = (const float*)d_in[0];
    const float* tgt = (const float*)d_in[1];
    float* out = (float*)d_out;
    (void)in_sizes; (void)n_in; (void)out_size;

    static int configured = 0;
    if (!configured) {
        cudaFuncSetAttribute(ray_kernel,
                             cudaFuncAttributeMaxDynamicSharedMemorySize,
                             SMEM_BYTES);
        configured = 1;
    }

    pad_kernel<<<(PW * PW + 255) / 256, 256>>>(in, tgt);
    ray_kernel<<<dim3(NSC, NDG, NAG), 1024, SMEM_BYTES>>>();
    raysum_kernel<<<NBLK_R, 256>>>();
    reduce_kernel<<<1, 1024>>>(out);
}

// round 11
// speedup vs baseline: 2.2069x; 1.1638x over previous
#include <cuda_runtime.h>
#include <cuda_fp16.h>
#include <math.h>

#define IMG    416
#define N_ANG  320
#define N_DET  416
#define N_SAMP 416
#define PAD    244
#define PW     904                  // IMG + 2*PAD
#define NRAY   (N_ANG * N_DET)      // 133120

#define AGRP   2                    // angles per block
#define NAG    (N_ANG / AGRP)       // 160
#define TD     64                   // detectors per block
#define TS     64                   // samples per chunk
#define NDG    7                    // ceil(416/64)
#define NSC    7                    // ceil(416/64)
#define WIN    168                  // staged window (span needs ~153 + margins)
#define WSTR   172                  // word stride; 172 mod 32 = 12 bank shift, mult of 4
#define SMEM_BYTES (WIN * WSTR * 4) // 115,584 B -> 2 CTAs/SM (227 KB limit)
#define NBLK_R 520                  // NRAY / 256

// Scratch: packed image, g_padh[i] = half2( v[i], v[i+1 within row] )
__device__ __align__(16) __half2 g_padh[PW * PW];   // ~3.27 MB
__device__ float  g_part[NSC * NRAY];               // per-(chunk, ray) partials
__device__ double g_blk[NBLK_R];

// ---------------------------------------------------------------------------
// Kernel 1: diff + zero-pad + pack into half2 pixel pairs.
// ---------------------------------------------------------------------------
__device__ __forceinline__ float diffv(const float* in, const float* tgt,
                                       int r, int c) {
    int rr = r - PAD;
    int cc = c - PAD;
    if (rr >= 0 && rr < IMG && cc >= 0 && cc < IMG) {
        int j = rr * IMG + cc;
        return in[j] - tgt[j];
    }
    return 0.0f;
}

__global__ void pad_kernel(const float* __restrict__ in,
                           const float* __restrict__ tgt) {
    int i = blockIdx.x * blockDim.x + threadIdx.x;
    if (i >= PW * PW) return;
    int r = i / PW;
    int c = i - r * PW;
    g_padh[i] = __floats2half2_rn(diffv(in, tgt, r, c), diffv(in, tgt, r, c + 1));
}

// ---------------------------------------------------------------------------
// Kernel 2: SMEM-staged fan-beam projection, 2 angles per staged window,
// 2 CTAs resident per SM so staging of one overlaps compute of the other.
// Block = (sample-chunk 64, det-group 64, angle-pair). 512 threads.
// Warp w (0..15): angle = ag*2 + (w & 1), det octet = w >> 1 in [0,7];
// lane = 8 dets x 4 sample-phases. 16 samples per thread.
// ---------------------------------------------------------------------------
__global__ void __launch_bounds__(512, 2) ray_kernel() {
    extern __shared__ __half2 smh[];
    __shared__ int sh_cmin, sh_rmin;

    const int chunk = blockIdx.x;   // 0..6
    const int dgrp  = blockIdx.y;   // 0..6
    const int ag    = blockIdx.z;   // 0..159
    const int tid   = threadIdx.x;

    const double hd_d   = 208.0 * sqrt(2.0);
    const double gmax_d = asin(hd_d / 1075.0);
    const float  THSTEP = (float)(2.0 * M_PI / 320.0);
    const float  GMAX   = (float)gmax_d;
    const float  DG     = (float)(2.0 * gmax_d / (N_DET - 1));
    const float  T0     = (float)(1075.0 - hd_d);
    const float  DTS    = (float)((2.0 * hd_d) / (N_SAMP - 1));
    const float  CTRP   = (float)((IMG - 1) * 0.5 + PAD);   // 451.5

    if (tid == 0) {
        int d_lo = dgrp * TD;
        int d_hi = min(d_lo + TD - 1, N_DET - 1);
        int s_lo = chunk * TS;
        int s_hi = min(s_lo + TS - 1, N_SAMP - 1);
        float g_lo = fmaf((float)d_lo, DG, -GMAX);
        float g_hi = fmaf((float)d_hi, DG, -GMAX);
        float t_lo = fmaf((float)s_lo, DTS, T0);
        float t_hi = fmaf((float)s_hi, DTS, T0);

        float xmin = 1e30f, ymin = 1e30f;
        #pragma unroll
        for (int k = 0; k < AGRP; k++) {
            float th = (float)(ag * AGRP + k) * THSTEP;
            float sth, cth;
            sincosf(th, &sth, &cth);
            float bx = fmaf(1075.0f, cth, CTRP);
            float by = fmaf(1075.0f, sth, CTRP);
            float s1, c1, s2, c2;
            sincosf(th + g_lo, &s1, &c1);
            sincosf(th + g_hi, &s2, &c2);
            xmin = fminf(xmin, fminf(fminf(fmaf(-t_lo, c1, bx), fmaf(-t_hi, c1, bx)),
                                     fminf(fmaf(-t_lo, c2, bx), fmaf(-t_hi, c2, bx))));
            ymin = fminf(ymin, fminf(fminf(fmaf(-t_lo, s1, by), fmaf(-t_hi, s1, by)),
                                     fminf(fmaf(-t_lo, s2, by), fmaf(-t_hi, s2, by))));
        }

        int cmin = (int)floorf(xmin) - 2;
        int rmin = (int)floorf(ymin) - 2;
        sh_cmin = max(0, min(cmin, PW - WIN)) & ~3;   // 16B-aligned for uint4
        sh_rmin = max(0, min(rmin, PW - WIN));
    }
    __syncthreads();

    const int cmin = sh_cmin;
    const int rmin = sh_rmin;

    // stage WIN x WIN half2 words via uint4 (4 words = 16 B; WIN/4 = 42)
    {
        const uint4* __restrict__ src =
            (const uint4*)(g_padh + rmin * PW + cmin);
        uint4* dst = (uint4*)smh;
        #pragma unroll 4
        for (int idx = tid; idx < WIN * (WIN / 4); idx += 512) {
            int rr = idx / (WIN / 4);
            int cc = idx - rr * (WIN / 4);
            dst[rr * (WSTR / 4) + cc] = src[rr * (PW / 4) + cc];
        }
    }
    __syncthreads();

    // compute
    const int warp   = tid >> 5;
    const int lane   = tid & 31;
    const int a      = ag * AGRP + (warp & 1);
    const int det    = dgrp * TD + (warp >> 1) * 8 + (lane >> 2);
    const int sphase = lane & 3;

    float acc = 0.0f;
    if (det < N_DET) {
        const float theta = (float)a * THSTEP;
        float sth, cth;
        sincosf(theta, &sth, &cth);
        const float gamma = fmaf((float)det, DG, -GMAX);
        float sph, cph;
        sincosf(theta + gamma, &sph, &cph);

        const float bxl  = fmaf(1075.0f, cth, CTRP) - (float)cmin;
        const float byl  = fmaf(1075.0f, sth, CTRP) - (float)rmin;
        const float ncph = -cph;
        const float nsph = -sph;

        const int s_base = chunk * TS + sphase;
        const int niter  = (chunk == NSC - 1) ? 8 : 16;  // last chunk: 32 samples

        #pragma unroll 8
        for (int i = 0; i < niter; i++) {
            float t  = fmaf((float)(s_base + 4 * i), DTS, T0);
            float x  = fmaf(t, ncph, bxl);
            float y  = fmaf(t, nsph, byl);
            float fx = floorf(x);
            float fy = floorf(y);
            float wc = x - fx;
            float wr = y - fy;
            int addr = (int)fy * WSTR + (int)fx;
            float2 tp = __half22float2(smh[addr]);          // (v00, v01)
            float2 bt = __half22float2(smh[addr + WSTR]);   // (v10, v11)
            float top = fmaf(wc, tp.y - tp.x, tp.x);
            float bot = fmaf(wc, bt.y - bt.x, bt.x);
            acc = fmaf(wr, bot - top, acc + top);
        }
    }

    // reduce 4 phases per detector
    acc += __shfl_xor_sync(0xFFFFFFFFu, acc, 1);
    acc += __shfl_xor_sync(0xFFFFFFFFu, acc, 2);

    if (sphase == 0 && det < N_DET) {
        g_part[chunk * NRAY + a * N_DET + det] = acc;
    }
}

// ---------------------------------------------------------------------------
// Kernel 3a: per-ray chunk sum + square, per-block tree reduce (double).
// ---------------------------------------------------------------------------
__global__ void raysum_kernel() {
    __shared__ double smr[256];
    const double hd_d = 208.0 * sqrt(2.0);
    const float  DTS  = (float)((2.0 * hd_d) / (N_SAMP - 1));
    int tid = threadIdx.x;
    int ray = blockIdx.x * 256 + tid;

    float v = 0.0f;
    #pragma unroll
    for (int s = 0; s < NSC; s++)
        v += g_part[s * NRAY + ray];
    float val = v * DTS;
    smr[tid] = (double)val * (double)val;
    __syncthreads();
    for (int stride = 128; stride > 0; stride >>= 1) {
        if (tid < stride) smr[tid] += smr[tid + stride];
        __syncthreads();
    }
    if (tid == 0) g_blk[blockIdx.x] = smr[0];
}

// ---------------------------------------------------------------------------
// Kernel 3b: final deterministic reduction -> mean * SCALE.
// ---------------------------------------------------------------------------
__global__ void reduce_kernel(float* __restrict__ out) {
    __shared__ double smr[1024];
    int tid = threadIdx.x;
    smr[tid] = (tid < NBLK_R) ? g_blk[tid] : 0.0;
    __syncthreads();
    for (int stride = 512; stride > 0; stride >>= 1) {
        if (tid < stride) smr[tid] += smr[tid + stride];
        __syncthreads();
    }
    if (tid == 0) {
        const double SCALE = 512.0 / 416.0 * 0.03;
        out[0] = (float)(smr[0] / (double)NRAY * SCALE);
    }
}

// ---------------------------------------------------------------------------
extern "C" void kernel_launch(void* const* d_in, const int* in_sizes, int n_in,
                              void* d_out, int out_size) {
    const float* in  = (const float*)d_in[0];
    const float* tgt = (const float*)d_in[1];
    float* out = (float*)d_out;
    (void)in_sizes; (void)n_in; (void)out_size;

    static int configured = 0;
    if (!configured) {
        cudaFuncSetAttribute(ray_kernel,
                             cudaFuncAttributeMaxDynamicSharedMemorySize,
                             SMEM_BYTES);
        configured = 1;
    }

    pad_kernel<<<(PW * PW + 255) / 256, 256>>>(in, tgt);
    ray_kernel<<<dim3(NSC, NDG, NAG), 512, SMEM_BYTES>>>();
    raysum_kernel<<<NBLK_R, 256>>>();
    reduce_kernel<<<1, 1024>>>(out);
}